// round 13
// baseline (speedup 1.0000x reference)
#include <cuda_runtime.h>
#include <cuda_bf16.h>
#include <math_constants.h>
#include <cstdint>

// Problem constants
#define Bq  2
#define Lq  2048
#define Dq  1024
#define Hq  16
#define HDq 64
#define Uq  8
#define SCALE 0.03125f   // 1/sqrt(1024), exact power of two
#define GAP_THRESH 4e-4f

#define NKT 32
#define NTILES (Lq / NKT)   // 64

typedef unsigned long long u64;
typedef unsigned int u32;

// ---------------- packed f32x2 helpers ----------------
__device__ __forceinline__ u64 ffma2(u64 a, u64 b, u64 c) {
    u64 d; asm("fma.rn.f32x2 %0, %1, %2, %3;" : "=l"(d) : "l"(a), "l"(b), "l"(c));
    return d;
}
__device__ __forceinline__ u64 fadd2(u64 a, u64 b) {
    u64 d; asm("add.rn.f32x2 %0, %1, %2;" : "=l"(d) : "l"(a), "l"(b));
    return d;
}
__device__ __forceinline__ void unpack2(u64 v, float& x, float& y) {
    asm("mov.b64 {%0, %1}, %2;" : "=f"(x), "=f"(y) : "l"(v));
}

// ---------------- warp MMA helpers ----------------
__device__ __forceinline__ u32 smem_u32(const void* p) {
    u32 a;
    asm("{ .reg .u64 t; cvta.to.shared.u64 t, %1; cvt.u32.u64 %0, t; }"
        : "=r"(a) : "l"(p));
    return a;
}
__device__ __forceinline__ void ldsm_x4(u32 addr, u32& r0, u32& r1, u32& r2, u32& r3) {
    asm volatile("ldmatrix.sync.aligned.m8n8.x4.shared.b16 {%0,%1,%2,%3}, [%4];"
                 : "=r"(r0), "=r"(r1), "=r"(r2), "=r"(r3) : "r"(addr));
}
__device__ __forceinline__ void ldsm_x2(u32 addr, u32& r0, u32& r1) {
    asm volatile("ldmatrix.sync.aligned.m8n8.x2.shared.b16 {%0,%1}, [%2];"
                 : "=r"(r0), "=r"(r1) : "r"(addr));
}
__device__ __forceinline__ void mma_bf16(float& c0, float& c1, float& c2, float& c3,
                                         u32 a0, u32 a1, u32 a2, u32 a3,
                                         u32 b0, u32 b1) {
    asm volatile(
        "mma.sync.aligned.m16n8k16.row.col.f32.bf16.bf16.f32 "
        "{%0,%1,%2,%3}, {%4,%5,%6,%7}, {%8,%9}, {%0,%1,%2,%3};"
        : "+f"(c0), "+f"(c1), "+f"(c2), "+f"(c3)
        : "r"(a0), "r"(a1), "r"(a2), "r"(a3), "r"(b0), "r"(b1));
}
__device__ __forceinline__ u32 cvt2bf(float hi, float lo) {
    u32 r; asm("cvt.rn.bf16x2.f32 %0, %1, %2;" : "=r"(r) : "f"(hi), "f"(lo));
    return r;
}

// top-N streaming insert (matches jax.lax.top_k; see R9 notes)
template<int N>
__device__ __forceinline__ void topN_insert(float (&tv)[N], int (&ti)[N],
                                            float& runmin, float s, int kidx) {
    if (s > runmin) {
        int m = 0; float mv = tv[0]; int mi = ti[0];
#pragma unroll
        for (int j = 1; j < N; j++) {
            bool take = (tv[j] < mv) || (tv[j] == mv && ti[j] > mi);
            if (take) { m = j; mv = tv[j]; mi = ti[j]; }
        }
#pragma unroll
        for (int j = 0; j < N; j++)
            if (j == m) { tv[j] = s; ti[j] = kidx; }
        float nm = tv[0];
#pragma unroll
        for (int j = 1; j < N; j++) nm = fminf(nm, tv[j]);
        runmin = nm;
    }
}

// Scratch context buffer
__device__ __align__(16) float g_ctx[(size_t)Bq * Lq * Dq];

// attn dynamic smem (32768 B) — same layout as R11 (validated)
#define KP1_OFF  4096
#define SC_OFF   12288
#define SW_OFF   0
#define SI_OFF   4096
#define RS_OFF   8192
#define RQ_OFF   16384
#define SL_OFF   20480
#define CN_OFF   20992
#define DSM_SZ   32768

// ---------------------------------------------------------------------------
__global__ __launch_bounds__(128) void attn_topk_kernel(
    const float* __restrict__ Q,
    const float* __restrict__ K,
    const float* __restrict__ V,
    float* __restrict__ attnw,
    int write_w)
{
    extern __shared__ __align__(16) char dsm[];
    const u32 sbase = smem_u32(dsm);
    int* s_list = (int*)(dsm + SL_OFF);
    int* s_cnt  = (int*)(dsm + CN_OFF);

    const int tid = threadIdx.x;
    const int lane = tid & 31;
    const int wrp = tid >> 5;
    const int b = blockIdx.z;
    const int h = blockIdx.y;
    const int qbase = blockIdx.x * 128;

    // ===== Phase 1: Q -> 2 bf16 planes in smem (swizzled, 128B rows) =====
    {
        const float4* qp = (const float4*)(Q + ((size_t)(b * Lq + qbase + tid)) * Dq + h * HDq);
        float r[64];
#pragma unroll
        for (int i = 0; i < 16; i++) {
            float4 t = qp[i];
            r[4 * i] = t.x; r[4 * i + 1] = t.y; r[4 * i + 2] = t.z; r[4 * i + 3] = t.w;
        }
#pragma unroll
        for (int p = 0; p < 2; p++) {
            u32 pk[32];
#pragma unroll
            for (int j = 0; j < 32; j++) {
                u32 c = cvt2bf(r[2 * j + 1], r[2 * j]);
                pk[j] = c;
                if (p < 1) {
                    r[2 * j]     -= __uint_as_float(c << 16);
                    r[2 * j + 1] -= __uint_as_float(c & 0xFFFF0000u);
                }
            }
#pragma unroll
            for (int i = 0; i < 8; i++) {
                u32 off = p * 16384 + tid * 128 + ((u32)(i ^ (tid & 7))) * 16;
                *(uint4*)(dsm + off) = *(uint4*)&pk[4 * i];
            }
        }
    }
    __syncthreads();

    // ===== Phase 2: A fragments -> registers (warp owns 32 queries) =====
    u32 A[2][2][4][4];
    {
        const int t4 = lane >> 3;
        const int r8 = lane & 7;
#pragma unroll
        for (int p = 0; p < 2; p++)
#pragma unroll
            for (int mt = 0; mt < 2; mt++)
#pragma unroll
                for (int ks = 0; ks < 4; ks++) {
                    u32 row = (u32)(wrp * 32 + mt * 16 + (t4 & 1) * 8 + r8);
                    u32 ch = (u32)(ks * 2 + (t4 >> 1));
                    u32 addr = sbase + p * 16384 + row * 128 + ((ch ^ (row & 7)) * 16);
                    ldsm_x4(addr, A[p][mt][ks][0], A[p][mt][ks][1],
                                  A[p][mt][ks][2], A[p][mt][ks][3]);
                }
    }
    __syncthreads();   // Q planes dead; K planes may overwrite

    // top-9 state per thread (query qbase + tid)
    float tv[9]; int ti[9]; float rmn = -CUDART_INF_F;
#pragma unroll
    for (int j = 0; j < 9; j++) { tv[j] = -CUDART_INF_F; ti[j] = 0; }

    float4* wz = (float4*)(attnw + ((size_t)((b * Hq + h) * Lq + qbase)) * Lq);

    // K staging: thread covers key tid>>2 (32 keys), dims (tid&3)*16 .. +15
    const int krow = tid >> 2;
    const int kd0 = (tid & 3) * 16;
    const int QP[3] = {0, 0, 1};
    const int KP[3] = {0, 1, 0};
    const int ll = lane & 15;

    // preload K tile 0 into staging registers (prefetch pipeline)
    float4 st[4];
    {
        const float4* kp = (const float4*)(K +
            ((size_t)(b * Lq + krow)) * Dq + h * HDq + kd0);
#pragma unroll
        for (int i = 0; i < 4; i++) st[i] = kp[i];
    }

    for (int t = 0; t < NTILES; t++) {
        // ---- convert staged K tile to 2 planes, STS swizzled ----
        {
            float e[16];
#pragma unroll
            for (int i = 0; i < 4; i++) {
                e[4 * i] = st[i].x; e[4 * i + 1] = st[i].y;
                e[4 * i + 2] = st[i].z; e[4 * i + 3] = st[i].w;
            }
            u32 p0[8], p1[8];
#pragma unroll
            for (int j = 0; j < 8; j++) {
                float a = e[2 * j], c = e[2 * j + 1];
                u32 v0 = cvt2bf(c, a);
                a -= __uint_as_float(v0 << 16);
                c -= __uint_as_float(v0 & 0xFFFF0000u);
                u32 v1 = cvt2bf(c, a);
                p0[j] = v0; p1[j] = v1;
            }
#pragma unroll
            for (int i = 0; i < 2; i++) {
                u32 ch = (u32)((tid & 3) * 2 + i);
                u32 off = (u32)krow * 128 + ((ch ^ ((u32)krow & 7)) * 16);
                *(uint4*)(dsm + off)           = *(uint4*)&p0[4 * i];
                *(uint4*)(dsm + KP1_OFF + off) = *(uint4*)&p1[4 * i];
            }
        }
        // prefetch next tile's fp32 K (hidden behind MMA + scan)
        if (t + 1 < NTILES) {
            const float4* kp = (const float4*)(K +
                ((size_t)(b * Lq + (t + 1) * NKT + krow)) * Dq + h * HDq + kd0);
#pragma unroll
            for (int i = 0; i < 4; i++) st[i] = kp[i];
        }
        // zero-fill this tile's slice of attnw (128 rows x 32 floats)
        if (write_w) {
            const float4 z = make_float4(0.f, 0.f, 0.f, 0.f);
            float4* zp = wz + (size_t)t * 1024;
#pragma unroll
            for (int i = 0; i < 8; i++) zp[i * 128 + tid] = z;
        }
        __syncthreads();   // K planes ready

        // ---- MMA: 4 n-tiles of 8 keys; scores -> smem [128][33] ----
#pragma unroll
        for (int nt = 0; nt < 4; nt++) {
            u32 Bf[2][4][2];
            {
                u32 row = (u32)(nt * 8 + (ll & 7));
                u32 swr = (row & 7);
#pragma unroll
                for (int ks = 0; ks < 4; ks++) {
                    u32 ch = (u32)(ks * 2 + (ll >> 3));
                    u32 off = row * 128 + ((ch ^ swr) * 16);
                    ldsm_x2(sbase + off,           Bf[0][ks][0], Bf[0][ks][1]);
                    ldsm_x2(sbase + KP1_OFF + off, Bf[1][ks][0], Bf[1][ks][1]);
                }
            }
            float cA0 = 0.f, cA1 = 0.f, cA2 = 0.f, cA3 = 0.f;
            float cB0 = 0.f, cB1 = 0.f, cB2 = 0.f, cB3 = 0.f;
#pragma unroll
            for (int pp = 0; pp < 3; pp++) {
                const int qp = QP[pp], kp2 = KP[pp];
#pragma unroll
                for (int ks = 0; ks < 4; ks++) {
                    mma_bf16(cA0, cA1, cA2, cA3,
                             A[qp][0][ks][0], A[qp][0][ks][1],
                             A[qp][0][ks][2], A[qp][0][ks][3],
                             Bf[kp2][ks][0], Bf[kp2][ks][1]);
                    mma_bf16(cB0, cB1, cB2, cB3,
                             A[qp][1][ks][0], A[qp][1][ks][1],
                             A[qp][1][ks][2], A[qp][1][ks][3],
                             Bf[kp2][ks][0], Bf[kp2][ks][1]);
                }
            }
            // scatter C frags to warp-private rows of the score buffer
            {
                const int q0 = wrp * 32 + (lane >> 2);
                const int kk = nt * 8 + (lane & 3) * 2;
                float* sc = (float*)(dsm + SC_OFF);
                sc[(q0 +  0) * 33 + kk]     = cA0;
                sc[(q0 +  0) * 33 + kk + 1] = cA1;
                sc[(q0 +  8) * 33 + kk]     = cA2;
                sc[(q0 +  8) * 33 + kk + 1] = cA3;
                sc[(q0 + 16) * 33 + kk]     = cB0;
                sc[(q0 + 16) * 33 + kk + 1] = cB1;
                sc[(q0 + 24) * 33 + kk]     = cB2;
                sc[(q0 + 24) * 33 + kk + 1] = cB3;
            }
        }
        __syncwarp();      // scores warp-private: scatter visible to own warp

        // ---- stream this thread's 32 scores (ascending keys), top-9 ----
        {
            const float* srow = (const float*)(dsm + SC_OFF) + tid * 33;
#pragma unroll 8
            for (int k = 0; k < NKT; k++) {
                float s = srow[k];
                topN_insert<9>(tv, ti, rmn, s, t * NKT + k);
            }
        }
        __syncthreads();   // scan + all K-plane reads done before next STS
    }

    // ===== init flag state =====
    if (tid == 0) *s_cnt = 0;
    __syncthreads();

    // ===== identify worst (9th); flag near-ties (8th-vs-9th gap) =====
    int w1 = 0;
    {
        float v1 = tv[0]; int i1 = ti[0];
#pragma unroll
        for (int j = 1; j < 9; j++) {
            bool worse = (tv[j] < v1) || (tv[j] == v1 && ti[j] > i1);
            if (worse) { w1 = j; v1 = tv[j]; i1 = ti[j]; }
        }
        float v2 = CUDART_INF_F;
#pragma unroll
        for (int j = 0; j < 9; j++)
            if (j != w1) v2 = fminf(v2, tv[j]);
        if (v2 - v1 < GAP_THRESH) {
            int idx = atomicAdd(s_cnt, 1);
            if (idx < 128) s_list[idx] = tid;
        }
    }

    // ===== softmax over the kept 8; write to sW/sI =====
    __syncthreads();
    {
        float kv[8]; int ki[8]; int c = 0;
#pragma unroll
        for (int j = 0; j < 9; j++)
            if (j != w1) { kv[c] = tv[j]; ki[c] = ti[j]; c++; }
        float mx = kv[0];
#pragma unroll
        for (int j = 1; j < 8; j++) mx = fmaxf(mx, kv[j]);
        float w[8]; float wsum = 0.f;
#pragma unroll
        for (int j = 0; j < 8; j++) { w[j] = expf((kv[j] - mx) * SCALE); wsum += w[j]; }
        float inv = 1.f / wsum;
        float* sW = (float*)(dsm + SW_OFF);
        int*   sI = (int*)(dsm + SI_OFF);
#pragma unroll
        for (int j = 0; j < 8; j++) { sW[tid * 8 + j] = w[j] * inv; sI[tid * 8 + j] = ki[j]; }
    }
    __syncthreads();

    // ===== rescue: recompute flagged rows with exact fp32 f32x2 chain =====
    {
        int ncnt = *s_cnt; if (ncnt > 128) ncnt = 128;
        float* sresc = (float*)(dsm + RS_OFF);
        float* qvec  = (float*)(dsm + RQ_OFF);
        for (int r = 0; r < ncnt; r++) {
            int qq = s_list[r];
            if (tid < 16)
                ((float4*)qvec)[tid] =
                    ((const float4*)(Q + ((size_t)(b * Lq + qbase + qq)) * Dq + h * HDq))[tid];
            __syncthreads();
            u64 q2[32];
            {
                const ulonglong2* qp2 = (const ulonglong2*)qvec;
#pragma unroll
                for (int i = 0; i < 16; i++) {
                    ulonglong2 v = qp2[i];
                    q2[2 * i] = v.x; q2[2 * i + 1] = v.y;
                }
            }
            for (int i = 0; i < 16; i++) {
                int kidx = tid + 128 * i;
                const ulonglong2* kp =
                    (const ulonglong2*)(K + ((size_t)(b * Lq + kidx)) * Dq + h * HDq);
                u64 a0 = 0ull, a1 = 0ull, a2 = 0ull, a3 = 0ull;
#pragma unroll
                for (int ii = 0; ii < 16; ii += 2) {
                    ulonglong2 k0 = kp[ii];
                    ulonglong2 k1 = kp[ii + 1];
                    a0 = ffma2(q2[2 * ii + 0], k0.x, a0);
                    a1 = ffma2(q2[2 * ii + 1], k0.y, a1);
                    a2 = ffma2(q2[2 * ii + 2], k1.x, a2);
                    a3 = ffma2(q2[2 * ii + 3], k1.y, a3);
                }
                u64 a = fadd2(fadd2(a0, a1), fadd2(a2, a3));
                float slo, shi; unpack2(a, slo, shi);
                sresc[kidx] = slo + shi;
            }
            __syncthreads();
            if (tid == 0) {
                float tv8[8]; int ti8[8]; float rm = -CUDART_INF_F;
#pragma unroll
                for (int j = 0; j < 8; j++) { tv8[j] = -CUDART_INF_F; ti8[j] = 0; }
                for (int k = 0; k < Lq; k++)
                    topN_insert<8>(tv8, ti8, rm, sresc[k], k);
                float mx = tv8[0];
#pragma unroll
                for (int j = 1; j < 8; j++) mx = fmaxf(mx, tv8[j]);
                float w8[8]; float wsum = 0.f;
#pragma unroll
                for (int j = 0; j < 8; j++) { w8[j] = expf((tv8[j] - mx) * SCALE); wsum += w8[j]; }
                float inv = 1.f / wsum;
                float* sW = (float*)(dsm + SW_OFF);
                int*   sI = (int*)(dsm + SI_OFF);
#pragma unroll
                for (int j = 0; j < 8; j++) { sW[qq * 8 + j] = w8[j] * inv; sI[qq * 8 + j] = ti8[j]; }
            }
            __syncthreads();
        }
    }

    // ===== scatter attn_weights =====
    if (write_w) {
        const float* sW = (const float*)(dsm + SW_OFF);
        const int*   sI = (const int*)(dsm + SI_OFF);
        float* wrow = attnw + ((size_t)((b * Hq + h) * Lq + qbase + tid)) * Lq;
#pragma unroll
        for (int j = 0; j < 8; j++) wrow[sI[tid * 8 + j]] = sW[tid * 8 + j];
    }

    // ===== coalesced V gather =====
    {
        const float* sW = (const float*)(dsm + SW_OFF);
        const int*   sI = (const int*)(dsm + SI_OFF);
        for (int qq = wrp * 32; qq < wrp * 32 + 32; qq++) {
            float2 acc = make_float2(0.f, 0.f);
#pragma unroll
            for (int j = 0; j < 8; j++) {
                float wv = sW[qq * 8 + j];
                int kidx = sI[qq * 8 + j];
                const float2* vp =
                    (const float2*)(V + ((size_t)(b * Lq + kidx)) * Dq + h * HDq);
                float2 vv = vp[lane];
                acc.x = fmaf(wv, vv.x, acc.x);
                acc.y = fmaf(wv, vv.y, acc.y);
            }
            float2* cp = (float2*)(g_ctx + ((size_t)(b * Lq + qbase + qq)) * Dq + h * HDq);
            cp[lane] = acc;
        }
    }
}

// ---------------------------------------------------------------------------
// Kernel 2: output projection via bf16 HMMA (same 2-plane/3-product scheme).
// out[m,n] = sum_k ctx[m,k]*W[n,k] + bias[n] — same Gram structure as scores.
// 256 threads, block tile 128(m) x 64(n), 16 k-chunks of 64.
// smem: A planes 0/16384 (128 rows x 128B), B planes 32768/40960 (64 rows).
// ---------------------------------------------------------------------------
#define PJ_A1  16384
#define PJ_B0  32768
#define PJ_B1  40960
#define PJ_DSM 49152

__global__ __launch_bounds__(256) void proj_mma_kernel(
    const float* __restrict__ Wt,
    const float* __restrict__ bias,
    float* __restrict__ Cout)
{
    extern __shared__ __align__(16) char pdsm[];
    const u32 sbase = smem_u32(pdsm);

    const int tid = threadIdx.x;
    const int lane = tid & 31;
    const int wrp = tid >> 5;
    const int m0 = blockIdx.y * 128;
    const int n0 = blockIdx.x * 64;

    const int arow = tid >> 1, akd = (tid & 1) * 32;   // A: 128 rows x 64 dims
    const int brow = tid >> 2, bkd = (tid & 3) * 16;   // B: 64 rows x 64 dims
    const int QP[3] = {0, 0, 1};
    const int KP[3] = {0, 1, 0};
    const int ll = lane & 15;

    // stage k-chunk 0
    float4 sa[8], sb[4];
    {
        const float4* ap = (const float4*)(g_ctx + (size_t)(m0 + arow) * Dq + akd);
#pragma unroll
        for (int i = 0; i < 8; i++) sa[i] = ap[i];
        const float4* bp = (const float4*)(Wt + (size_t)(n0 + brow) * Dq + bkd);
#pragma unroll
        for (int i = 0; i < 4; i++) sb[i] = bp[i];
    }

    float C[8][4];
#pragma unroll
    for (int i = 0; i < 8; i++)
#pragma unroll
        for (int j = 0; j < 4; j++) C[i][j] = 0.f;

    for (int kc = 0; kc < 16; kc++) {
        // ---- convert A chunk (2 planes), STS swizzled ----
        {
            float e[32];
#pragma unroll
            for (int i = 0; i < 8; i++) {
                e[4 * i] = sa[i].x; e[4 * i + 1] = sa[i].y;
                e[4 * i + 2] = sa[i].z; e[4 * i + 3] = sa[i].w;
            }
            u32 p0[16], p1[16];
#pragma unroll
            for (int j = 0; j < 16; j++) {
                float a = e[2 * j], c = e[2 * j + 1];
                u32 v0 = cvt2bf(c, a);
                a -= __uint_as_float(v0 << 16);
                c -= __uint_as_float(v0 & 0xFFFF0000u);
                u32 v1 = cvt2bf(c, a);
                p0[j] = v0; p1[j] = v1;
            }
#pragma unroll
            for (int i = 0; i < 4; i++) {
                u32 ch = (u32)((tid & 1) * 4 + i);
                u32 off = (u32)arow * 128 + ((ch ^ ((u32)arow & 7)) * 16);
                *(uint4*)(pdsm + off)          = *(uint4*)&p0[4 * i];
                *(uint4*)(pdsm + PJ_A1 + off)  = *(uint4*)&p1[4 * i];
            }
        }
        // ---- convert B chunk (2 planes), STS swizzled ----
        {
            float e[16];
#pragma unroll
            for (int i = 0; i < 4; i++) {
                e[4 * i] = sb[i].x; e[4 * i + 1] = sb[i].y;
                e[4 * i + 2] = sb[i].z; e[4 * i + 3] = sb[i].w;
            }
            u32 p0[8], p1[8];
#pragma unroll
            for (int j = 0; j < 8; j++) {
                float a = e[2 * j], c = e[2 * j + 1];
                u32 v0 = cvt2bf(c, a);
                a -= __uint_as_float(v0 << 16);
                c -= __uint_as_float(v0 & 0xFFFF0000u);
                u32 v1 = cvt2bf(c, a);
                p0[j] = v0; p1[j] = v1;
            }
#pragma unroll
            for (int i = 0; i < 2; i++) {
                u32 ch = (u32)((tid & 3) * 2 + i);
                u32 off = (u32)brow * 128 + ((ch ^ ((u32)brow & 7)) * 16);
                *(uint4*)(pdsm + PJ_B0 + off) = *(uint4*)&p0[4 * i];
                *(uint4*)(pdsm + PJ_B1 + off) = *(uint4*)&p1[4 * i];
            }
        }
        // prefetch next chunk (hidden behind MMA)
        if (kc + 1 < 16) {
            const float4* ap = (const float4*)(g_ctx +
                (size_t)(m0 + arow) * Dq + (kc + 1) * 64 + akd);
#pragma unroll
            for (int i = 0; i < 8; i++) sa[i] = ap[i];
            const float4* bp = (const float4*)(Wt +
                (size_t)(n0 + brow) * Dq + (kc + 1) * 64 + bkd);
#pragma unroll
            for (int i = 0; i < 4; i++) sb[i] = bp[i];
        }
        __syncthreads();   // planes ready

        // ---- A fragments: warp covers m rows wrp*16..+15 ----
        u32 Af[2][4][4];
        {
            const int t4 = lane >> 3;
            const int r8 = lane & 7;
#pragma unroll
            for (int p = 0; p < 2; p++)
#pragma unroll
                for (int ks = 0; ks < 4; ks++) {
                    u32 row = (u32)(wrp * 16 + (t4 & 1) * 8 + r8);
                    u32 ch = (u32)(ks * 2 + (t4 >> 1));
                    u32 addr = sbase + (p ? PJ_A1 : 0) + row * 128 + ((ch ^ (row & 7)) * 16);
                    ldsm_x4(addr, Af[p][ks][0], Af[p][ks][1], Af[p][ks][2], Af[p][ks][3]);
                }
        }

        // ---- 8 n-tiles of 8 output cols ----
#pragma unroll
        for (int nt = 0; nt < 8; nt++) {
            u32 Bf[2][4][2];
            {
                u32 row = (u32)(nt * 8 + (ll & 7));
                u32 swr = (row & 7);
#pragma unroll
                for (int ks = 0; ks < 4; ks++) {
                    u32 ch = (u32)(ks * 2 + (ll >> 3));
                    u32 off = row * 128 + ((ch ^ swr) * 16);
                    ldsm_x2(sbase + PJ_B0 + off, Bf[0][ks][0], Bf[0][ks][1]);
                    ldsm_x2(sbase + PJ_B1 + off, Bf[1][ks][0], Bf[1][ks][1]);
                }
            }
#pragma unroll
            for (int pp = 0; pp < 3; pp++) {
                const int qp = QP[pp], kp2 = KP[pp];
#pragma unroll
                for (int ks = 0; ks < 4; ks++)
                    mma_bf16(C[nt][0], C[nt][1], C[nt][2], C[nt][3],
                             Af[qp][ks][0], Af[qp][ks][1],
                             Af[qp][ks][2], Af[qp][ks][3],
                             Bf[kp2][ks][0], Bf[kp2][ks][1]);
            }
        }
        __syncthreads();   // all ldsm done before next chunk's STS
    }

    // ---- epilogue: C frag layout -> global + bias ----
#pragma unroll
    for (int nt = 0; nt < 8; nt++) {
        int n = n0 + nt * 8 + (lane & 3) * 2;
        int m = m0 + wrp * 16 + (lane >> 2);
        float2 bb = *(const float2*)&bias[n];
        float2 r0 = make_float2(C[nt][0] + bb.x, C[nt][1] + bb.y);
        float2 r1 = make_float2(C[nt][2] + bb.x, C[nt][3] + bb.y);
        *(float2*)&Cout[(size_t)m * Dq + n] = r0;
        *(float2*)&Cout[(size_t)(m + 8) * Dq + n] = r1;
    }
}

// ---------------------------------------------------------------------------
extern "C" void kernel_launch(void* const* d_in, const int* in_sizes, int n_in,
                              void* d_out, int out_size)
{
    const float* Q    = (const float*)d_in[0];
    const float* K    = (const float*)d_in[1];
    const float* V    = (const float*)d_in[2];
    const float* W    = (const float*)d_in[3];
    const float* bias = (const float*)d_in[4];
    float* out = (float*)d_out;

    const size_t N_ATT = (size_t)Bq * Lq * Dq;
    const size_t N_W   = (size_t)Bq * Hq * Lq * Lq;
    const int has_w = ((size_t)out_size >= N_ATT + N_W) ? 1 : 0;
    float* attnw = out + N_ATT;

    dim3 g1(Lq / 128, Hq, Bq);
    attn_topk_kernel<<<g1, 128, DSM_SZ>>>(Q, K, V, attnw, has_w);

    dim3 g2(Dq / 64, (Bq * Lq) / 128);
    proj_mma_kernel<<<g2, 256, PJ_DSM>>>(W, bias, out);
}

// round 14
// speedup vs baseline: 1.2124x; 1.2124x over previous
#include <cuda_runtime.h>
#include <cuda_bf16.h>
#include <math_constants.h>
#include <cstdint>

// Problem constants
#define Bq  2
#define Lq  2048
#define Dq  1024
#define Hq  16
#define HDq 64
#define Uq  8
#define SCALE 0.03125f   // 1/sqrt(1024), exact power of two
#define GAP_THRESH 4e-4f

#define NKT 32
#define NTILES (Lq / NKT)   // 64

typedef unsigned long long u64;
typedef unsigned int u32;

// ---------------- packed f32x2 helpers ----------------
__device__ __forceinline__ u64 ffma2(u64 a, u64 b, u64 c) {
    u64 d; asm("fma.rn.f32x2 %0, %1, %2, %3;" : "=l"(d) : "l"(a), "l"(b), "l"(c));
    return d;
}
__device__ __forceinline__ u64 fadd2(u64 a, u64 b) {
    u64 d; asm("add.rn.f32x2 %0, %1, %2;" : "=l"(d) : "l"(a), "l"(b));
    return d;
}
__device__ __forceinline__ void unpack2(u64 v, float& x, float& y) {
    asm("mov.b64 {%0, %1}, %2;" : "=f"(x), "=f"(y) : "l"(v));
}

// ---------------- warp MMA helpers ----------------
__device__ __forceinline__ u32 smem_u32(const void* p) {
    u32 a;
    asm("{ .reg .u64 t; cvta.to.shared.u64 t, %1; cvt.u32.u64 %0, t; }"
        : "=r"(a) : "l"(p));
    return a;
}
__device__ __forceinline__ void ldsm_x4(u32 addr, u32& r0, u32& r1, u32& r2, u32& r3) {
    asm volatile("ldmatrix.sync.aligned.m8n8.x4.shared.b16 {%0,%1,%2,%3}, [%4];"
                 : "=r"(r0), "=r"(r1), "=r"(r2), "=r"(r3) : "r"(addr));
}
__device__ __forceinline__ void ldsm_x2(u32 addr, u32& r0, u32& r1) {
    asm volatile("ldmatrix.sync.aligned.m8n8.x2.shared.b16 {%0,%1}, [%2];"
                 : "=r"(r0), "=r"(r1) : "r"(addr));
}
__device__ __forceinline__ void mma_bf16(float& c0, float& c1, float& c2, float& c3,
                                         u32 a0, u32 a1, u32 a2, u32 a3,
                                         u32 b0, u32 b1) {
    asm volatile(
        "mma.sync.aligned.m16n8k16.row.col.f32.bf16.bf16.f32 "
        "{%0,%1,%2,%3}, {%4,%5,%6,%7}, {%8,%9}, {%0,%1,%2,%3};"
        : "+f"(c0), "+f"(c1), "+f"(c2), "+f"(c3)
        : "r"(a0), "r"(a1), "r"(a2), "r"(a3), "r"(b0), "r"(b1));
}
__device__ __forceinline__ u32 cvt2bf(float hi, float lo) {
    u32 r; asm("cvt.rn.bf16x2.f32 %0, %1, %2;" : "=r"(r) : "f"(hi), "f"(lo));
    return r;
}

// top-N streaming insert (matches jax.lax.top_k tie semantics)
template<int N>
__device__ __forceinline__ void topN_insert(float (&tv)[N], int (&ti)[N],
                                            float& runmin, float s, int kidx) {
    if (s > runmin) {
        int m = 0; float mv = tv[0]; int mi = ti[0];
#pragma unroll
        for (int j = 1; j < N; j++) {
            bool take = (tv[j] < mv) || (tv[j] == mv && ti[j] > mi);
            if (take) { m = j; mv = tv[j]; mi = ti[j]; }
        }
#pragma unroll
        for (int j = 0; j < N; j++)
            if (j == m) { tv[j] = s; ti[j] = kidx; }
        float nm = tv[0];
#pragma unroll
        for (int j = 1; j < N; j++) nm = fminf(nm, tv[j]);
        runmin = nm;
    }
}

// Scratch context buffer
__device__ __align__(16) float g_ctx[(size_t)Bq * Lq * Dq];

// attn dynamic smem (32768 B) — R11-validated layout
#define KP1_OFF  4096
#define SC_OFF   12288
#define SW_OFF   0
#define SI_OFF   4096
#define RS_OFF   8192
#define RQ_OFF   16384
#define SL_OFF   20480
#define CN_OFF   20992
#define DSM_SZ   32768

// ---------------------------------------------------------------------------
// Kernel 1 (R11 verbatim): HMMA scores (2-plane/3-product), per-thread top-9,
// gap flag + exact fp32 rescue, softmax, attnw zero-fill + scatter, V gather.
// NO K-tile register prefetch (regressed twice: R3, R12).
// ---------------------------------------------------------------------------
__global__ __launch_bounds__(128) void attn_topk_kernel(
    const float* __restrict__ Q,
    const float* __restrict__ K,
    const float* __restrict__ V,
    float* __restrict__ attnw,
    int write_w)
{
    extern __shared__ __align__(16) char dsm[];
    const u32 sbase = smem_u32(dsm);
    int* s_list = (int*)(dsm + SL_OFF);
    int* s_cnt  = (int*)(dsm + CN_OFF);

    const int tid = threadIdx.x;
    const int lane = tid & 31;
    const int wrp = tid >> 5;
    const int b = blockIdx.z;
    const int h = blockIdx.y;
    const int qbase = blockIdx.x * 128;

    // ===== Phase 1: Q -> 2 bf16 planes in smem (swizzled, 128B rows) =====
    {
        const float4* qp = (const float4*)(Q + ((size_t)(b * Lq + qbase + tid)) * Dq + h * HDq);
        float r[64];
#pragma unroll
        for (int i = 0; i < 16; i++) {
            float4 t = qp[i];
            r[4 * i] = t.x; r[4 * i + 1] = t.y; r[4 * i + 2] = t.z; r[4 * i + 3] = t.w;
        }
#pragma unroll
        for (int p = 0; p < 2; p++) {
            u32 pk[32];
#pragma unroll
            for (int j = 0; j < 32; j++) {
                u32 c = cvt2bf(r[2 * j + 1], r[2 * j]);
                pk[j] = c;
                if (p < 1) {
                    r[2 * j]     -= __uint_as_float(c << 16);
                    r[2 * j + 1] -= __uint_as_float(c & 0xFFFF0000u);
                }
            }
#pragma unroll
            for (int i = 0; i < 8; i++) {
                u32 off = p * 16384 + tid * 128 + ((u32)(i ^ (tid & 7))) * 16;
                *(uint4*)(dsm + off) = *(uint4*)&pk[4 * i];
            }
        }
    }
    __syncthreads();

    // ===== Phase 2: A fragments -> registers (warp owns 32 queries) =====
    u32 A[2][2][4][4];
    {
        const int t4 = lane >> 3;
        const int r8 = lane & 7;
#pragma unroll
        for (int p = 0; p < 2; p++)
#pragma unroll
            for (int mt = 0; mt < 2; mt++)
#pragma unroll
                for (int ks = 0; ks < 4; ks++) {
                    u32 row = (u32)(wrp * 32 + mt * 16 + (t4 & 1) * 8 + r8);
                    u32 ch = (u32)(ks * 2 + (t4 >> 1));
                    u32 addr = sbase + p * 16384 + row * 128 + ((ch ^ (row & 7)) * 16);
                    ldsm_x4(addr, A[p][mt][ks][0], A[p][mt][ks][1],
                                  A[p][mt][ks][2], A[p][mt][ks][3]);
                }
    }
    __syncthreads();   // Q planes dead; K planes may overwrite

    // top-9 state per thread (query qbase + tid)
    float tv[9]; int ti[9]; float rmn = -CUDART_INF_F;
#pragma unroll
    for (int j = 0; j < 9; j++) { tv[j] = -CUDART_INF_F; ti[j] = 0; }

    float4* wz = (float4*)(attnw + ((size_t)((b * Hq + h) * Lq + qbase)) * Lq);

    // K staging: thread covers key tid>>2 (32 keys), dims (tid&3)*16 .. +15
    const int krow = tid >> 2;
    const int kd0 = (tid & 3) * 16;
    const int QP[3] = {0, 0, 1};
    const int KP[3] = {0, 1, 0};
    const int ll = lane & 15;

    for (int t = 0; t < NTILES; t++) {
        // ---- load K tile fp32 (32 keys x 64 dims), split to 2 planes ----
        {
            const float4* kp = (const float4*)(K +
                ((size_t)(b * Lq + t * NKT + krow)) * Dq + h * HDq + kd0);
            float e[16];
#pragma unroll
            for (int i = 0; i < 4; i++) {
                float4 v = kp[i];
                e[4 * i] = v.x; e[4 * i + 1] = v.y; e[4 * i + 2] = v.z; e[4 * i + 3] = v.w;
            }
            u32 p0[8], p1[8];
#pragma unroll
            for (int j = 0; j < 8; j++) {
                float a = e[2 * j], c = e[2 * j + 1];
                u32 v0 = cvt2bf(c, a);
                a -= __uint_as_float(v0 << 16);
                c -= __uint_as_float(v0 & 0xFFFF0000u);
                u32 v1 = cvt2bf(c, a);
                p0[j] = v0; p1[j] = v1;
            }
#pragma unroll
            for (int i = 0; i < 2; i++) {
                u32 ch = (u32)((tid & 3) * 2 + i);
                u32 off = (u32)krow * 128 + ((ch ^ ((u32)krow & 7)) * 16);
                *(uint4*)(dsm + off)           = *(uint4*)&p0[4 * i];
                *(uint4*)(dsm + KP1_OFF + off) = *(uint4*)&p1[4 * i];
            }
        }
        // zero-fill this tile's slice of attnw (128 rows x 32 floats)
        if (write_w) {
            const float4 z = make_float4(0.f, 0.f, 0.f, 0.f);
            float4* zp = wz + (size_t)t * 1024;
#pragma unroll
            for (int i = 0; i < 8; i++) zp[i * 128 + tid] = z;
        }
        __syncthreads();   // K planes ready

        // ---- MMA: 4 n-tiles of 8 keys; scores -> smem [128][33] ----
#pragma unroll
        for (int nt = 0; nt < 4; nt++) {
            u32 Bf[2][4][2];
            {
                u32 row = (u32)(nt * 8 + (ll & 7));
                u32 swr = (row & 7);
#pragma unroll
                for (int ks = 0; ks < 4; ks++) {
                    u32 ch = (u32)(ks * 2 + (ll >> 3));
                    u32 off = row * 128 + ((ch ^ swr) * 16);
                    ldsm_x2(sbase + off,           Bf[0][ks][0], Bf[0][ks][1]);
                    ldsm_x2(sbase + KP1_OFF + off, Bf[1][ks][0], Bf[1][ks][1]);
                }
            }
            float cA0 = 0.f, cA1 = 0.f, cA2 = 0.f, cA3 = 0.f;
            float cB0 = 0.f, cB1 = 0.f, cB2 = 0.f, cB3 = 0.f;
#pragma unroll
            for (int pp = 0; pp < 3; pp++) {
                const int qp = QP[pp], kp2 = KP[pp];
#pragma unroll
                for (int ks = 0; ks < 4; ks++) {
                    mma_bf16(cA0, cA1, cA2, cA3,
                             A[qp][0][ks][0], A[qp][0][ks][1],
                             A[qp][0][ks][2], A[qp][0][ks][3],
                             Bf[kp2][ks][0], Bf[kp2][ks][1]);
                    mma_bf16(cB0, cB1, cB2, cB3,
                             A[qp][1][ks][0], A[qp][1][ks][1],
                             A[qp][1][ks][2], A[qp][1][ks][3],
                             Bf[kp2][ks][0], Bf[kp2][ks][1]);
                }
            }
            // scatter C frags to warp-private rows of the score buffer
            {
                const int q0 = wrp * 32 + (lane >> 2);
                const int kk = nt * 8 + (lane & 3) * 2;
                float* sc = (float*)(dsm + SC_OFF);
                sc[(q0 +  0) * 33 + kk]     = cA0;
                sc[(q0 +  0) * 33 + kk + 1] = cA1;
                sc[(q0 +  8) * 33 + kk]     = cA2;
                sc[(q0 +  8) * 33 + kk + 1] = cA3;
                sc[(q0 + 16) * 33 + kk]     = cB0;
                sc[(q0 + 16) * 33 + kk + 1] = cB1;
                sc[(q0 + 24) * 33 + kk]     = cB2;
                sc[(q0 + 24) * 33 + kk + 1] = cB3;
            }
        }
        __syncwarp();      // scores warp-private: scatter visible to own warp

        // ---- stream this thread's 32 scores (ascending keys), top-9 ----
        {
            const float* srow = (const float*)(dsm + SC_OFF) + tid * 33;
#pragma unroll 8
            for (int k = 0; k < NKT; k++) {
                float s = srow[k];
                topN_insert<9>(tv, ti, rmn, s, t * NKT + k);
            }
        }
        __syncthreads();   // scan + all K-plane reads done before next STS
    }

    // ===== init flag state =====
    if (tid == 0) *s_cnt = 0;
    __syncthreads();

    // ===== identify worst (9th); flag near-ties (8th-vs-9th gap) =====
    int w1 = 0;
    {
        float v1 = tv[0]; int i1 = ti[0];
#pragma unroll
        for (int j = 1; j < 9; j++) {
            bool worse = (tv[j] < v1) || (tv[j] == v1 && ti[j] > i1);
            if (worse) { w1 = j; v1 = tv[j]; i1 = ti[j]; }
        }
        float v2 = CUDART_INF_F;
#pragma unroll
        for (int j = 0; j < 9; j++)
            if (j != w1) v2 = fminf(v2, tv[j]);
        if (v2 - v1 < GAP_THRESH) {
            int idx = atomicAdd(s_cnt, 1);
            if (idx < 128) s_list[idx] = tid;
        }
    }

    // ===== softmax over the kept 8; write to sW/sI =====
    __syncthreads();
    {
        float kv[8]; int ki[8]; int c = 0;
#pragma unroll
        for (int j = 0; j < 9; j++)
            if (j != w1) { kv[c] = tv[j]; ki[c] = ti[j]; c++; }
        float mx = kv[0];
#pragma unroll
        for (int j = 1; j < 8; j++) mx = fmaxf(mx, kv[j]);
        float w[8]; float wsum = 0.f;
#pragma unroll
        for (int j = 0; j < 8; j++) { w[j] = expf((kv[j] - mx) * SCALE); wsum += w[j]; }
        float inv = 1.f / wsum;
        float* sW = (float*)(dsm + SW_OFF);
        int*   sI = (int*)(dsm + SI_OFF);
#pragma unroll
        for (int j = 0; j < 8; j++) { sW[tid * 8 + j] = w[j] * inv; sI[tid * 8 + j] = ki[j]; }
    }
    __syncthreads();

    // ===== rescue: recompute flagged rows with exact fp32 f32x2 chain =====
    {
        int ncnt = *s_cnt; if (ncnt > 128) ncnt = 128;
        float* sresc = (float*)(dsm + RS_OFF);
        float* qvec  = (float*)(dsm + RQ_OFF);
        for (int r = 0; r < ncnt; r++) {
            int qq = s_list[r];
            if (tid < 16)
                ((float4*)qvec)[tid] =
                    ((const float4*)(Q + ((size_t)(b * Lq + qbase + qq)) * Dq + h * HDq))[tid];
            __syncthreads();
            u64 q2[32];
            {
                const ulonglong2* qp2 = (const ulonglong2*)qvec;
#pragma unroll
                for (int i = 0; i < 16; i++) {
                    ulonglong2 v = qp2[i];
                    q2[2 * i] = v.x; q2[2 * i + 1] = v.y;
                }
            }
            for (int i = 0; i < 16; i++) {
                int kidx = tid + 128 * i;
                const ulonglong2* kp =
                    (const ulonglong2*)(K + ((size_t)(b * Lq + kidx)) * Dq + h * HDq);
                u64 a0 = 0ull, a1 = 0ull, a2 = 0ull, a3 = 0ull;
#pragma unroll
                for (int ii = 0; ii < 16; ii += 2) {
                    ulonglong2 k0 = kp[ii];
                    ulonglong2 k1 = kp[ii + 1];
                    a0 = ffma2(q2[2 * ii + 0], k0.x, a0);
                    a1 = ffma2(q2[2 * ii + 1], k0.y, a1);
                    a2 = ffma2(q2[2 * ii + 2], k1.x, a2);
                    a3 = ffma2(q2[2 * ii + 3], k1.y, a3);
                }
                u64 a = fadd2(fadd2(a0, a1), fadd2(a2, a3));
                float slo, shi; unpack2(a, slo, shi);
                sresc[kidx] = slo + shi;
            }
            __syncthreads();
            if (tid == 0) {
                float tv8[8]; int ti8[8]; float rm = -CUDART_INF_F;
#pragma unroll
                for (int j = 0; j < 8; j++) { tv8[j] = -CUDART_INF_F; ti8[j] = 0; }
                for (int k = 0; k < Lq; k++)
                    topN_insert<8>(tv8, ti8, rm, sresc[k], k);
                float mx = tv8[0];
#pragma unroll
                for (int j = 1; j < 8; j++) mx = fmaxf(mx, tv8[j]);
                float w8[8]; float wsum = 0.f;
#pragma unroll
                for (int j = 0; j < 8; j++) { w8[j] = expf((tv8[j] - mx) * SCALE); wsum += w8[j]; }
                float inv = 1.f / wsum;
                float* sW = (float*)(dsm + SW_OFF);
                int*   sI = (int*)(dsm + SI_OFF);
#pragma unroll
                for (int j = 0; j < 8; j++) { sW[qq * 8 + j] = w8[j] * inv; sI[qq * 8 + j] = ti8[j]; }
            }
            __syncthreads();
        }
    }

    // ===== scatter attn_weights =====
    if (write_w) {
        const float* sW = (const float*)(dsm + SW_OFF);
        const int*   sI = (const int*)(dsm + SI_OFF);
        float* wrow = attnw + ((size_t)((b * Hq + h) * Lq + qbase + tid)) * Lq;
#pragma unroll
        for (int j = 0; j < 8; j++) wrow[sI[tid * 8 + j]] = sW[tid * 8 + j];
    }

    // ===== coalesced V gather =====
    {
        const float* sW = (const float*)(dsm + SW_OFF);
        const int*   sI = (const int*)(dsm + SI_OFF);
        for (int qq = wrp * 32; qq < wrp * 32 + 32; qq++) {
            float2 acc = make_float2(0.f, 0.f);
#pragma unroll
            for (int j = 0; j < 8; j++) {
                float wv = sW[qq * 8 + j];
                int kidx = sI[qq * 8 + j];
                const float2* vp =
                    (const float2*)(V + ((size_t)(b * Lq + kidx)) * Dq + h * HDq);
                float2 vv = vp[lane];
                acc.x = fmaf(wv, vv.x, acc.x);
                acc.y = fmaf(wv, vv.y, acc.y);
            }
            float2* cp = (float2*)(g_ctx + ((size_t)(b * Lq + qbase + qq)) * Dq + h * HDq);
            cp[lane] = acc;
        }
    }
}

// ---------------------------------------------------------------------------
// Kernel 2 (R12 verbatim): projection via bf16 HMMA, 2-plane/3-product.
// 256 threads, tile 128(m) x 64(n), 16 k-chunks of 64.
// ---------------------------------------------------------------------------
#define PJ_A1  16384
#define PJ_B0  32768
#define PJ_B1  40960
#define PJ_DSM 49152

__global__ __launch_bounds__(256) void proj_mma_kernel(
    const float* __restrict__ Wt,
    const float* __restrict__ bias,
    float* __restrict__ Cout)
{
    extern __shared__ __align__(16) char pdsm[];
    const u32 sbase = smem_u32(pdsm);

    const int tid = threadIdx.x;
    const int lane = tid & 31;
    const int wrp = tid >> 5;
    const int m0 = blockIdx.y * 128;
    const int n0 = blockIdx.x * 64;

    const int arow = tid >> 1, akd = (tid & 1) * 32;
    const int brow = tid >> 2, bkd = (tid & 3) * 16;
    const int QP[3] = {0, 0, 1};
    const int KP[3] = {0, 1, 0};
    const int ll = lane & 15;

    float4 sa[8], sb[4];
    {
        const float4* ap = (const float4*)(g_ctx + (size_t)(m0 + arow) * Dq + akd);
#pragma unroll
        for (int i = 0; i < 8; i++) sa[i] = ap[i];
        const float4* bp = (const float4*)(Wt + (size_t)(n0 + brow) * Dq + bkd);
#pragma unroll
        for (int i = 0; i < 4; i++) sb[i] = bp[i];
    }

    float C[8][4];
#pragma unroll
    for (int i = 0; i < 8; i++)
#pragma unroll
        for (int j = 0; j < 4; j++) C[i][j] = 0.f;

    for (int kc = 0; kc < 16; kc++) {
        // ---- convert A chunk (2 planes), STS swizzled ----
        {
            float e[32];
#pragma unroll
            for (int i = 0; i < 8; i++) {
                e[4 * i] = sa[i].x; e[4 * i + 1] = sa[i].y;
                e[4 * i + 2] = sa[i].z; e[4 * i + 3] = sa[i].w;
            }
            u32 p0[16], p1[16];
#pragma unroll
            for (int j = 0; j < 16; j++) {
                float a = e[2 * j], c = e[2 * j + 1];
                u32 v0 = cvt2bf(c, a);
                a -= __uint_as_float(v0 << 16);
                c -= __uint_as_float(v0 & 0xFFFF0000u);
                u32 v1 = cvt2bf(c, a);
                p0[j] = v0; p1[j] = v1;
            }
#pragma unroll
            for (int i = 0; i < 4; i++) {
                u32 ch = (u32)((tid & 1) * 4 + i);
                u32 off = (u32)arow * 128 + ((ch ^ ((u32)arow & 7)) * 16);
                *(uint4*)(pdsm + off)          = *(uint4*)&p0[4 * i];
                *(uint4*)(pdsm + PJ_A1 + off)  = *(uint4*)&p1[4 * i];
            }
        }
        // ---- convert B chunk (2 planes), STS swizzled ----
        {
            float e[16];
#pragma unroll
            for (int i = 0; i < 4; i++) {
                e[4 * i] = sb[i].x; e[4 * i + 1] = sb[i].y;
                e[4 * i + 2] = sb[i].z; e[4 * i + 3] = sb[i].w;
            }
            u32 p0[8], p1[8];
#pragma unroll
            for (int j = 0; j < 8; j++) {
                float a = e[2 * j], c = e[2 * j + 1];
                u32 v0 = cvt2bf(c, a);
                a -= __uint_as_float(v0 << 16);
                c -= __uint_as_float(v0 & 0xFFFF0000u);
                u32 v1 = cvt2bf(c, a);
                p0[j] = v0; p1[j] = v1;
            }
#pragma unroll
            for (int i = 0; i < 2; i++) {
                u32 ch = (u32)((tid & 3) * 2 + i);
                u32 off = (u32)brow * 128 + ((ch ^ ((u32)brow & 7)) * 16);
                *(uint4*)(pdsm + PJ_B0 + off) = *(uint4*)&p0[4 * i];
                *(uint4*)(pdsm + PJ_B1 + off) = *(uint4*)&p1[4 * i];
            }
        }
        // prefetch next chunk (hidden behind MMA)
        if (kc + 1 < 16) {
            const float4* ap = (const float4*)(g_ctx +
                (size_t)(m0 + arow) * Dq + (kc + 1) * 64 + akd);
#pragma unroll
            for (int i = 0; i < 8; i++) sa[i] = ap[i];
            const float4* bp = (const float4*)(Wt +
                (size_t)(n0 + brow) * Dq + (kc + 1) * 64 + bkd);
#pragma unroll
            for (int i = 0; i < 4; i++) sb[i] = bp[i];
        }
        __syncthreads();   // planes ready

        // ---- A fragments: warp covers m rows wrp*16..+15 ----
        u32 Af[2][4][4];
        {
            const int t4 = lane >> 3;
            const int r8 = lane & 7;
#pragma unroll
            for (int p = 0; p < 2; p++)
#pragma unroll
                for (int ks = 0; ks < 4; ks++) {
                    u32 row = (u32)(wrp * 16 + (t4 & 1) * 8 + r8);
                    u32 ch = (u32)(ks * 2 + (t4 >> 1));
                    u32 addr = sbase + (p ? PJ_A1 : 0) + row * 128 + ((ch ^ (row & 7)) * 16);
                    ldsm_x4(addr, Af[p][ks][0], Af[p][ks][1], Af[p][ks][2], Af[p][ks][3]);
                }
        }

        // ---- 8 n-tiles of 8 output cols ----
#pragma unroll
        for (int nt = 0; nt < 8; nt++) {
            u32 Bf[2][4][2];
            {
                u32 row = (u32)(nt * 8 + (ll & 7));
                u32 swr = (row & 7);
#pragma unroll
                for (int ks = 0; ks < 4; ks++) {
                    u32 ch = (u32)(ks * 2 + (ll >> 3));
                    u32 off = row * 128 + ((ch ^ swr) * 16);
                    ldsm_x2(sbase + PJ_B0 + off, Bf[0][ks][0], Bf[0][ks][1]);
                    ldsm_x2(sbase + PJ_B1 + off, Bf[1][ks][0], Bf[1][ks][1]);
                }
            }
#pragma unroll
            for (int pp = 0; pp < 3; pp++) {
                const int qp = QP[pp], kp2 = KP[pp];
#pragma unroll
                for (int ks = 0; ks < 4; ks++)
                    mma_bf16(C[nt][0], C[nt][1], C[nt][2], C[nt][3],
                             Af[qp][ks][0], Af[qp][ks][1],
                             Af[qp][ks][2], Af[qp][ks][3],
                             Bf[kp2][ks][0], Bf[kp2][ks][1]);
            }
        }
        __syncthreads();   // all ldsm done before next chunk's STS
    }

    // ---- epilogue: C frag layout -> global + bias ----
#pragma unroll
    for (int nt = 0; nt < 8; nt++) {
        int n = n0 + nt * 8 + (lane & 3) * 2;
        int m = m0 + wrp * 16 + (lane >> 2);
        float2 bb = *(const float2*)&bias[n];
        float2 r0 = make_float2(C[nt][0] + bb.x, C[nt][1] + bb.y);
        float2 r1 = make_float2(C[nt][2] + bb.x, C[nt][3] + bb.y);
        *(float2*)&Cout[(size_t)m * Dq + n] = r0;
        *(float2*)&Cout[(size_t)(m + 8) * Dq + n] = r1;
    }
}

// ---------------------------------------------------------------------------
extern "C" void kernel_launch(void* const* d_in, const int* in_sizes, int n_in,
                              void* d_out, int out_size)
{
    const float* Q    = (const float*)d_in[0];
    const float* K    = (const float*)d_in[1];
    const float* V    = (const float*)d_in[2];
    const float* W    = (const float*)d_in[3];
    const float* bias = (const float*)d_in[4];
    float* out = (float*)d_out;

    const size_t N_ATT = (size_t)Bq * Lq * Dq;
    const size_t N_W   = (size_t)Bq * Hq * Lq * Lq;
    const int has_w = ((size_t)out_size >= N_ATT + N_W) ? 1 : 0;
    float* attnw = out + N_ATT;

    dim3 g1(Lq / 128, Hq, Bq);
    attn_topk_kernel<<<g1, 128, DSM_SZ>>>(Q, K, V, attnw, has_w);

    dim3 g2(Dq / 64, (Bq * Lq) / 128);
    proj_mma_kernel<<<g2, 256, PJ_DSM>>>(W, bias, out);
}

// round 15
// speedup vs baseline: 1.2738x; 1.0507x over previous
#include <cuda_runtime.h>
#include <cuda_bf16.h>
#include <math_constants.h>
#include <cstdint>

// Problem constants
#define Bq  2
#define Lq  2048
#define Dq  1024
#define Hq  16
#define HDq 64
#define Uq  8
#define SCALE 0.03125f   // 1/sqrt(1024), exact power of two
#define GAP_THRESH 4e-4f

#define NKT 32
#define NTILES (Lq / NKT)   // 64

typedef unsigned long long u64;
typedef unsigned int u32;

// ---------------- packed f32x2 helpers ----------------
__device__ __forceinline__ u64 ffma2(u64 a, u64 b, u64 c) {
    u64 d; asm("fma.rn.f32x2 %0, %1, %2, %3;" : "=l"(d) : "l"(a), "l"(b), "l"(c));
    return d;
}
__device__ __forceinline__ u64 fadd2(u64 a, u64 b) {
    u64 d; asm("add.rn.f32x2 %0, %1, %2;" : "=l"(d) : "l"(a), "l"(b));
    return d;
}
__device__ __forceinline__ void unpack2(u64 v, float& x, float& y) {
    asm("mov.b64 {%0, %1}, %2;" : "=f"(x), "=f"(y) : "l"(v));
}

// ---------------- warp MMA helpers ----------------
__device__ __forceinline__ u32 smem_u32(const void* p) {
    u32 a;
    asm("{ .reg .u64 t; cvta.to.shared.u64 t, %1; cvt.u32.u64 %0, t; }"
        : "=r"(a) : "l"(p));
    return a;
}
__device__ __forceinline__ void ldsm_x4(u32 addr, u32& r0, u32& r1, u32& r2, u32& r3) {
    asm volatile("ldmatrix.sync.aligned.m8n8.x4.shared.b16 {%0,%1,%2,%3}, [%4];"
                 : "=r"(r0), "=r"(r1), "=r"(r2), "=r"(r3) : "r"(addr));
}
__device__ __forceinline__ void ldsm_x2(u32 addr, u32& r0, u32& r1) {
    asm volatile("ldmatrix.sync.aligned.m8n8.x2.shared.b16 {%0,%1}, [%2];"
                 : "=r"(r0), "=r"(r1) : "r"(addr));
}
__device__ __forceinline__ void mma_bf16(float& c0, float& c1, float& c2, float& c3,
                                         u32 a0, u32 a1, u32 a2, u32 a3,
                                         u32 b0, u32 b1) {
    asm volatile(
        "mma.sync.aligned.m16n8k16.row.col.f32.bf16.bf16.f32 "
        "{%0,%1,%2,%3}, {%4,%5,%6,%7}, {%8,%9}, {%0,%1,%2,%3};"
        : "+f"(c0), "+f"(c1), "+f"(c2), "+f"(c3)
        : "r"(a0), "r"(a1), "r"(a2), "r"(a3), "r"(b0), "r"(b1));
}
__device__ __forceinline__ u32 cvt2bf(float hi, float lo) {
    u32 r; asm("cvt.rn.bf16x2.f32 %0, %1, %2;" : "=r"(r) : "f"(hi), "f"(lo));
    return r;
}

// top-N streaming insert (matches jax.lax.top_k tie semantics)
template<int N>
__device__ __forceinline__ void topN_insert(float (&tv)[N], int (&ti)[N],
                                            float& runmin, float s, int kidx) {
    if (s > runmin) {
        int m = 0; float mv = tv[0]; int mi = ti[0];
#pragma unroll
        for (int j = 1; j < N; j++) {
            bool take = (tv[j] < mv) || (tv[j] == mv && ti[j] > mi);
            if (take) { m = j; mv = tv[j]; mi = ti[j]; }
        }
#pragma unroll
        for (int j = 0; j < N; j++)
            if (j == m) { tv[j] = s; ti[j] = kidx; }
        float nm = tv[0];
#pragma unroll
        for (int j = 1; j < N; j++) nm = fminf(nm, tv[j]);
        runmin = nm;
    }
}

// Scratch context buffer
__device__ __align__(16) float g_ctx[(size_t)Bq * Lq * Dq];

// attn dynamic smem (33280 B, zero static):
//  phase Q : 2 planes at 0 / 16384 (128 rows x 128B, swizzled; ends 32768)
//  main    : DOUBLE-BUFFERED K planes: buf b at b*8192 (p0) / b*8192+4096 (p1);
//            scores f32 [128][33] at 16384 (16896B -> ends 33280).
//            One block barrier per tile: STS(t) targets the idle buffer, so
//            no "reads done" barrier is needed before the next tile's STS.
//  post    : sW [128][8] at 0, sI at 4096, rescue scores 8192..16384,
//            qvec at 16384, s_list at 20480, s_cnt 20992 (all dead regions)
#define SC_OFF   16384
#define SW_OFF   0
#define SI_OFF   4096
#define RS_OFF   8192
#define RQ_OFF   16384
#define SL_OFF   20480
#define CN_OFF   20992
#define DSM_SZ   33280

// ---------------------------------------------------------------------------
// Kernel 1: HMMA scores (2-plane/3-product), per-thread top-9, gap flag +
// exact fp32 rescue, softmax, attnw zero-fill + scatter, V gather.
// ---------------------------------------------------------------------------
__global__ __launch_bounds__(128) void attn_topk_kernel(
    const float* __restrict__ Q,
    const float* __restrict__ K,
    const float* __restrict__ V,
    float* __restrict__ attnw,
    int write_w)
{
    extern __shared__ __align__(16) char dsm[];
    const u32 sbase = smem_u32(dsm);
    int* s_list = (int*)(dsm + SL_OFF);
    int* s_cnt  = (int*)(dsm + CN_OFF);

    const int tid = threadIdx.x;
    const int lane = tid & 31;
    const int wrp = tid >> 5;
    const int b = blockIdx.z;
    const int h = blockIdx.y;
    const int qbase = blockIdx.x * 128;

    // ===== Phase 1: Q -> 2 bf16 planes in smem (swizzled, 128B rows) =====
    {
        const float4* qp = (const float4*)(Q + ((size_t)(b * Lq + qbase + tid)) * Dq + h * HDq);
        float r[64];
#pragma unroll
        for (int i = 0; i < 16; i++) {
            float4 t = qp[i];
            r[4 * i] = t.x; r[4 * i + 1] = t.y; r[4 * i + 2] = t.z; r[4 * i + 3] = t.w;
        }
#pragma unroll
        for (int p = 0; p < 2; p++) {
            u32 pk[32];
#pragma unroll
            for (int j = 0; j < 32; j++) {
                u32 c = cvt2bf(r[2 * j + 1], r[2 * j]);
                pk[j] = c;
                if (p < 1) {
                    r[2 * j]     -= __uint_as_float(c << 16);
                    r[2 * j + 1] -= __uint_as_float(c & 0xFFFF0000u);
                }
            }
#pragma unroll
            for (int i = 0; i < 8; i++) {
                u32 off = p * 16384 + tid * 128 + ((u32)(i ^ (tid & 7))) * 16;
                *(uint4*)(dsm + off) = *(uint4*)&pk[4 * i];
            }
        }
    }
    __syncthreads();

    // ===== Phase 2: A fragments -> registers (warp owns 32 queries) =====
    u32 A[2][2][4][4];
    {
        const int t4 = lane >> 3;
        const int r8 = lane & 7;
#pragma unroll
        for (int p = 0; p < 2; p++)
#pragma unroll
            for (int mt = 0; mt < 2; mt++)
#pragma unroll
                for (int ks = 0; ks < 4; ks++) {
                    u32 row = (u32)(wrp * 32 + mt * 16 + (t4 & 1) * 8 + r8);
                    u32 ch = (u32)(ks * 2 + (t4 >> 1));
                    u32 addr = sbase + p * 16384 + row * 128 + ((ch ^ (row & 7)) * 16);
                    ldsm_x4(addr, A[p][mt][ks][0], A[p][mt][ks][1],
                                  A[p][mt][ks][2], A[p][mt][ks][3]);
                }
    }
    __syncthreads();   // Q planes dead; K planes may overwrite

    // top-9 state per thread (query qbase + tid)
    float tv[9]; int ti[9]; float rmn = -CUDART_INF_F;
#pragma unroll
    for (int j = 0; j < 9; j++) { tv[j] = -CUDART_INF_F; ti[j] = 0; }

    float4* wz = (float4*)(attnw + ((size_t)((b * Hq + h) * Lq + qbase)) * Lq);

    // K staging: thread covers key tid>>2 (32 keys), dims (tid&3)*16 .. +15
    const int krow = tid >> 2;
    const int kd0 = (tid & 3) * 16;
    const int QP[3] = {0, 0, 1};
    const int KP[3] = {0, 1, 0};
    const int ll = lane & 15;

    for (int t = 0; t < NTILES; t++) {
        const u32 kb = (u32)(t & 1) * 8192;   // this tile's plane buffer

        // ---- load K tile fp32 (32 keys x 64 dims), split to 2 planes ----
        {
            const float4* kp = (const float4*)(K +
                ((size_t)(b * Lq + t * NKT + krow)) * Dq + h * HDq + kd0);
            float e[16];
#pragma unroll
            for (int i = 0; i < 4; i++) {
                float4 v = kp[i];
                e[4 * i] = v.x; e[4 * i + 1] = v.y; e[4 * i + 2] = v.z; e[4 * i + 3] = v.w;
            }
            u32 p0[8], p1[8];
#pragma unroll
            for (int j = 0; j < 8; j++) {
                float a = e[2 * j], c = e[2 * j + 1];
                u32 v0 = cvt2bf(c, a);
                a -= __uint_as_float(v0 << 16);
                c -= __uint_as_float(v0 & 0xFFFF0000u);
                u32 v1 = cvt2bf(c, a);
                p0[j] = v0; p1[j] = v1;
            }
#pragma unroll
            for (int i = 0; i < 2; i++) {
                u32 ch = (u32)((tid & 3) * 2 + i);
                u32 off = (u32)krow * 128 + ((ch ^ ((u32)krow & 7)) * 16);
                *(uint4*)(dsm + kb + off)        = *(uint4*)&p0[4 * i];
                *(uint4*)(dsm + kb + 4096 + off) = *(uint4*)&p1[4 * i];
            }
        }
        // zero-fill this tile's slice of attnw (128 rows x 32 floats)
        if (write_w) {
            const float4 z = make_float4(0.f, 0.f, 0.f, 0.f);
            float4* zp = wz + (size_t)t * 1024;
#pragma unroll
            for (int i = 0; i < 8; i++) zp[i * 128 + tid] = z;
        }
        __syncthreads();   // K planes (this buffer) ready; ONLY barrier per tile

        // ---- MMA: 4 n-tiles of 8 keys; scores -> smem [128][33] ----
#pragma unroll
        for (int nt = 0; nt < 4; nt++) {
            u32 Bf[2][4][2];
            {
                u32 row = (u32)(nt * 8 + (ll & 7));
                u32 swr = (row & 7);
#pragma unroll
                for (int ks = 0; ks < 4; ks++) {
                    u32 ch = (u32)(ks * 2 + (ll >> 3));
                    u32 off = row * 128 + ((ch ^ swr) * 16);
                    ldsm_x2(sbase + kb + off,        Bf[0][ks][0], Bf[0][ks][1]);
                    ldsm_x2(sbase + kb + 4096 + off, Bf[1][ks][0], Bf[1][ks][1]);
                }
            }
            float cA0 = 0.f, cA1 = 0.f, cA2 = 0.f, cA3 = 0.f;
            float cB0 = 0.f, cB1 = 0.f, cB2 = 0.f, cB3 = 0.f;
#pragma unroll
            for (int pp = 0; pp < 3; pp++) {
                const int qp = QP[pp], kp2 = KP[pp];
#pragma unroll
                for (int ks = 0; ks < 4; ks++) {
                    mma_bf16(cA0, cA1, cA2, cA3,
                             A[qp][0][ks][0], A[qp][0][ks][1],
                             A[qp][0][ks][2], A[qp][0][ks][3],
                             Bf[kp2][ks][0], Bf[kp2][ks][1]);
                    mma_bf16(cB0, cB1, cB2, cB3,
                             A[qp][1][ks][0], A[qp][1][ks][1],
                             A[qp][1][ks][2], A[qp][1][ks][3],
                             Bf[kp2][ks][0], Bf[kp2][ks][1]);
                }
            }
            // scatter C frags to warp-private rows of the score buffer
            {
                const int q0 = wrp * 32 + (lane >> 2);
                const int kk = nt * 8 + (lane & 3) * 2;
                float* sc = (float*)(dsm + SC_OFF);
                sc[(q0 +  0) * 33 + kk]     = cA0;
                sc[(q0 +  0) * 33 + kk + 1] = cA1;
                sc[(q0 +  8) * 33 + kk]     = cA2;
                sc[(q0 +  8) * 33 + kk + 1] = cA3;
                sc[(q0 + 16) * 33 + kk]     = cB0;
                sc[(q0 + 16) * 33 + kk + 1] = cB1;
                sc[(q0 + 24) * 33 + kk]     = cB2;
                sc[(q0 + 24) * 33 + kk + 1] = cB3;
            }
        }
        __syncwarp();      // scores warp-private: scatter visible to own warp

        // ---- stream this thread's 32 scores (ascending keys), top-9 ----
        {
            const float* srow = (const float*)(dsm + SC_OFF) + tid * 33;
#pragma unroll 8
            for (int k = 0; k < NKT; k++) {
                float s = srow[k];
                topN_insert<9>(tv, ti, rmn, s, t * NKT + k);
            }
        }
        // no trailing barrier: next tile's STS targets the other buffer, and
        // next tile's scatter (same warp) is ordered after this scan.
    }

    // ===== init flag state =====
    __syncthreads();
    if (tid == 0) *s_cnt = 0;
    __syncthreads();

    // ===== identify worst (9th); flag near-ties (8th-vs-9th gap) =====
    int w1 = 0;
    {
        float v1 = tv[0]; int i1 = ti[0];
#pragma unroll
        for (int j = 1; j < 9; j++) {
            bool worse = (tv[j] < v1) || (tv[j] == v1 && ti[j] > i1);
            if (worse) { w1 = j; v1 = tv[j]; i1 = ti[j]; }
        }
        float v2 = CUDART_INF_F;
#pragma unroll
        for (int j = 0; j < 9; j++)
            if (j != w1) v2 = fminf(v2, tv[j]);
        if (v2 - v1 < GAP_THRESH) {
            int idx = atomicAdd(s_cnt, 1);
            if (idx < 128) s_list[idx] = tid;
        }
    }

    // ===== softmax over the kept 8; write to sW/sI =====
    __syncthreads();
    {
        float kv[8]; int ki[8]; int c = 0;
#pragma unroll
        for (int j = 0; j < 9; j++)
            if (j != w1) { kv[c] = tv[j]; ki[c] = ti[j]; c++; }
        float mx = kv[0];
#pragma unroll
        for (int j = 1; j < 8; j++) mx = fmaxf(mx, kv[j]);
        float w[8]; float wsum = 0.f;
#pragma unroll
        for (int j = 0; j < 8; j++) { w[j] = expf((kv[j] - mx) * SCALE); wsum += w[j]; }
        float inv = 1.f / wsum;
        float* sW = (float*)(dsm + SW_OFF);
        int*   sI = (int*)(dsm + SI_OFF);
#pragma unroll
        for (int j = 0; j < 8; j++) { sW[tid * 8 + j] = w[j] * inv; sI[tid * 8 + j] = ki[j]; }
    }
    __syncthreads();

    // ===== rescue: recompute flagged rows with exact fp32 f32x2 chain =====
    {
        int ncnt = *s_cnt; if (ncnt > 128) ncnt = 128;
        float* sresc = (float*)(dsm + RS_OFF);
        float* qvec  = (float*)(dsm + RQ_OFF);
        for (int r = 0; r < ncnt; r++) {
            int qq = s_list[r];
            if (tid < 16)
                ((float4*)qvec)[tid] =
                    ((const float4*)(Q + ((size_t)(b * Lq + qbase + qq)) * Dq + h * HDq))[tid];
            __syncthreads();
            u64 q2[32];
            {
                const ulonglong2* qp2 = (const ulonglong2*)qvec;
#pragma unroll
                for (int i = 0; i < 16; i++) {
                    ulonglong2 v = qp2[i];
                    q2[2 * i] = v.x; q2[2 * i + 1] = v.y;
                }
            }
            for (int i = 0; i < 16; i++) {
                int kidx = tid + 128 * i;
                const ulonglong2* kp =
                    (const ulonglong2*)(K + ((size_t)(b * Lq + kidx)) * Dq + h * HDq);
                u64 a0 = 0ull, a1 = 0ull, a2 = 0ull, a3 = 0ull;
#pragma unroll
                for (int ii = 0; ii < 16; ii += 2) {
                    ulonglong2 k0 = kp[ii];
                    ulonglong2 k1 = kp[ii + 1];
                    a0 = ffma2(q2[2 * ii + 0], k0.x, a0);
                    a1 = ffma2(q2[2 * ii + 1], k0.y, a1);
                    a2 = ffma2(q2[2 * ii + 2], k1.x, a2);
                    a3 = ffma2(q2[2 * ii + 3], k1.y, a3);
                }
                u64 a = fadd2(fadd2(a0, a1), fadd2(a2, a3));
                float slo, shi; unpack2(a, slo, shi);
                sresc[kidx] = slo + shi;
            }
            __syncthreads();
            if (tid == 0) {
                float tv8[8]; int ti8[8]; float rm = -CUDART_INF_F;
#pragma unroll
                for (int j = 0; j < 8; j++) { tv8[j] = -CUDART_INF_F; ti8[j] = 0; }
                for (int k = 0; k < Lq; k++)
                    topN_insert<8>(tv8, ti8, rm, sresc[k], k);
                float mx = tv8[0];
#pragma unroll
                for (int j = 1; j < 8; j++) mx = fmaxf(mx, tv8[j]);
                float w8[8]; float wsum = 0.f;
#pragma unroll
                for (int j = 0; j < 8; j++) { w8[j] = expf((tv8[j] - mx) * SCALE); wsum += w8[j]; }
                float inv = 1.f / wsum;
                float* sW = (float*)(dsm + SW_OFF);
                int*   sI = (int*)(dsm + SI_OFF);
#pragma unroll
                for (int j = 0; j < 8; j++) { sW[qq * 8 + j] = w8[j] * inv; sI[qq * 8 + j] = ti8[j]; }
            }
            __syncthreads();
        }
    }

    // ===== scatter attn_weights =====
    if (write_w) {
        const float* sW = (const float*)(dsm + SW_OFF);
        const int*   sI = (const int*)(dsm + SI_OFF);
        float* wrow = attnw + ((size_t)((b * Hq + h) * Lq + qbase + tid)) * Lq;
#pragma unroll
        for (int j = 0; j < 8; j++) wrow[sI[tid * 8 + j]] = sW[tid * 8 + j];
    }

    // ===== coalesced V gather =====
    {
        const float* sW = (const float*)(dsm + SW_OFF);
        const int*   sI = (const int*)(dsm + SI_OFF);
        for (int qq = wrp * 32; qq < wrp * 32 + 32; qq++) {
            float2 acc = make_float2(0.f, 0.f);
#pragma unroll
            for (int j = 0; j < 8; j++) {
                float wv = sW[qq * 8 + j];
                int kidx = sI[qq * 8 + j];
                const float2* vp =
                    (const float2*)(V + ((size_t)(b * Lq + kidx)) * Dq + h * HDq);
                float2 vv = vp[lane];
                acc.x = fmaf(wv, vv.x, acc.x);
                acc.y = fmaf(wv, vv.y, acc.y);
            }
            float2* cp = (float2*)(g_ctx + ((size_t)(b * Lq + qbase + qq)) * Dq + h * HDq);
            cp[lane] = acc;
        }
    }
}

// ---------------------------------------------------------------------------
// Kernel 2: projection via bf16 HMMA, 2-plane/3-product.
// NO register prefetch; __launch_bounds__(256, 2) -> 2 CTAs/SM for
// cross-CTA latency hiding (regs were the 1-CTA limiter at 170).
// ---------------------------------------------------------------------------
#define PJ_A1  16384
#define PJ_B0  32768
#define PJ_B1  40960
#define PJ_DSM 49152

__global__ __launch_bounds__(256, 2) void proj_mma_kernel(
    const float* __restrict__ Wt,
    const float* __restrict__ bias,
    float* __restrict__ Cout)
{
    extern __shared__ __align__(16) char pdsm[];
    const u32 sbase = smem_u32(pdsm);

    const int tid = threadIdx.x;
    const int lane = tid & 31;
    const int wrp = tid >> 5;
    const int m0 = blockIdx.y * 128;
    const int n0 = blockIdx.x * 64;

    const int arow = tid >> 1, akd = (tid & 1) * 32;
    const int brow = tid >> 2, bkd = (tid & 3) * 16;
    const int QP[3] = {0, 0, 1};
    const int KP[3] = {0, 1, 0};
    const int ll = lane & 15;

    float C[8][4];
#pragma unroll
    for (int i = 0; i < 8; i++)
#pragma unroll
        for (int j = 0; j < 4; j++) C[i][j] = 0.f;

    for (int kc = 0; kc < 16; kc++) {
        if (kc > 0) __syncthreads();   // previous chunk's planes consumed

        // ---- load + convert A chunk (2 planes), STS swizzled ----
        {
            const float4* ap = (const float4*)(g_ctx +
                (size_t)(m0 + arow) * Dq + kc * 64 + akd);
            float e[32];
#pragma unroll
            for (int i = 0; i < 8; i++) {
                float4 v = ap[i];
                e[4 * i] = v.x; e[4 * i + 1] = v.y;
                e[4 * i + 2] = v.z; e[4 * i + 3] = v.w;
            }
            u32 p0[16], p1[16];
#pragma unroll
            for (int j = 0; j < 16; j++) {
                float a = e[2 * j], c = e[2 * j + 1];
                u32 v0 = cvt2bf(c, a);
                a -= __uint_as_float(v0 << 16);
                c -= __uint_as_float(v0 & 0xFFFF0000u);
                u32 v1 = cvt2bf(c, a);
                p0[j] = v0; p1[j] = v1;
            }
#pragma unroll
            for (int i = 0; i < 4; i++) {
                u32 ch = (u32)((tid & 1) * 4 + i);
                u32 off = (u32)arow * 128 + ((ch ^ ((u32)arow & 7)) * 16);
                *(uint4*)(pdsm + off)          = *(uint4*)&p0[4 * i];
                *(uint4*)(pdsm + PJ_A1 + off)  = *(uint4*)&p1[4 * i];
            }
        }
        // ---- load + convert B chunk (2 planes), STS swizzled ----
        {
            const float4* bp = (const float4*)(Wt +
                (size_t)(n0 + brow) * Dq + kc * 64 + bkd);
            float e[16];
#pragma unroll
            for (int i = 0; i < 4; i++) {
                float4 v = bp[i];
                e[4 * i] = v.x; e[4 * i + 1] = v.y;
                e[4 * i + 2] = v.z; e[4 * i + 3] = v.w;
            }
            u32 p0[8], p1[8];
#pragma unroll
            for (int j = 0; j < 8; j++) {
                float a = e[2 * j], c = e[2 * j + 1];
                u32 v0 = cvt2bf(c, a);
                a -= __uint_as_float(v0 << 16);
                c -= __uint_as_float(v0 & 0xFFFF0000u);
                u32 v1 = cvt2bf(c, a);
                p0[j] = v0; p1[j] = v1;
            }
#pragma unroll
            for (int i = 0; i < 2; i++) {
                u32 ch = (u32)((tid & 3) * 2 + i);
                u32 off = (u32)brow * 128 + ((ch ^ ((u32)brow & 7)) * 16);
                *(uint4*)(pdsm + PJ_B0 + off) = *(uint4*)&p0[4 * i];
                *(uint4*)(pdsm + PJ_B1 + off) = *(uint4*)&p1[4 * i];
            }
        }
        __syncthreads();   // planes ready

        // ---- A fragments: warp covers m rows wrp*16..+15 ----
        u32 Af[2][4][4];
        {
            const int t4 = lane >> 3;
            const int r8 = lane & 7;
#pragma unroll
            for (int p = 0; p < 2; p++)
#pragma unroll
                for (int ks = 0; ks < 4; ks++) {
                    u32 row = (u32)(wrp * 16 + (t4 & 1) * 8 + r8);
                    u32 ch = (u32)(ks * 2 + (t4 >> 1));
                    u32 addr = sbase + (p ? PJ_A1 : 0) + row * 128 + ((ch ^ (row & 7)) * 16);
                    ldsm_x4(addr, Af[p][ks][0], Af[p][ks][1], Af[p][ks][2], Af[p][ks][3]);
                }
        }

        // ---- 8 n-tiles of 8 output cols ----
#pragma unroll
        for (int nt = 0; nt < 8; nt++) {
            u32 Bf[2][4][2];
            {
                u32 row = (u32)(nt * 8 + (ll & 7));
                u32 swr = (row & 7);
#pragma unroll
                for (int ks = 0; ks < 4; ks++) {
                    u32 ch = (u32)(ks * 2 + (ll >> 3));
                    u32 off = row * 128 + ((ch ^ swr) * 16);
                    ldsm_x2(sbase + PJ_B0 + off, Bf[0][ks][0], Bf[0][ks][1]);
                    ldsm_x2(sbase + PJ_B1 + off, Bf[1][ks][0], Bf[1][ks][1]);
                }
            }
#pragma unroll
            for (int pp = 0; pp < 3; pp++) {
                const int qp = QP[pp], kp2 = KP[pp];
#pragma unroll
                for (int ks = 0; ks < 4; ks++)
                    mma_bf16(C[nt][0], C[nt][1], C[nt][2], C[nt][3],
                             Af[qp][ks][0], Af[qp][ks][1],
                             Af[qp][ks][2], Af[qp][ks][3],
                             Bf[kp2][ks][0], Bf[kp2][ks][1]);
            }
        }
    }

    // ---- epilogue: C frag layout -> global + bias ----
#pragma unroll
    for (int nt = 0; nt < 8; nt++) {
        int n = n0 + nt * 8 + (lane & 3) * 2;
        int m = m0 + wrp * 16 + (lane >> 2);
        float2 bb = *(const float2*)&bias[n];
        float2 r0 = make_float2(C[nt][0] + bb.x, C[nt][1] + bb.y);
        float2 r1 = make_float2(C[nt][2] + bb.x, C[nt][3] + bb.y);
        *(float2*)&Cout[(size_t)m * Dq + n] = r0;
        *(float2*)&Cout[(size_t)(m + 8) * Dq + n] = r1;
    }
}

// ---------------------------------------------------------------------------
extern "C" void kernel_launch(void* const* d_in, const int* in_sizes, int n_in,
                              void* d_out, int out_size)
{
    const float* Q    = (const float*)d_in[0];
    const float* K    = (const float*)d_in[1];
    const float* V    = (const float*)d_in[2];
    const float* W    = (const float*)d_in[3];
    const float* bias = (const float*)d_in[4];
    float* out = (float*)d_out;

    const size_t N_ATT = (size_t)Bq * Lq * Dq;
    const size_t N_W   = (size_t)Bq * Hq * Lq * Lq;
    const int has_w = ((size_t)out_size >= N_ATT + N_W) ? 1 : 0;
    float* attnw = out + N_ATT;

    dim3 g1(Lq / 128, Hq, Bq);
    attn_topk_kernel<<<g1, 128, DSM_SZ>>>(Q, K, V, attnw, has_w);

    dim3 g2(Dq / 64, (Bq * Lq) / 128);
    proj_mma_kernel<<<g2, 256, PJ_DSM>>>(W, bias, out);
}